// round 6
// baseline (speedup 1.0000x reference)
#include <cuda_runtime.h>
#include <cstdint>

// GPT2Editor: softmax over a size-1 axis -> weights == 1, so
// out[s, :] = sum_f ( (h_last @ Wc[f][:, E:2E] + bc[f][E:]) @ Wp[f] + bp[f] )
// broadcast to all 4096 rows. Dead inputs: encoder_hidden_states, Wq, bq.
// E = 2048, F = 4.

#define EDIM 2048
#define FDIM 4
#define SOUT 4096
#define ECHUNK 16
#define NCHUNK (EDIM / ECHUNK)   // 128

__device__ float g_v[FDIM * EDIM];  // v rows, one per f
__device__ float g_r[EDIM];         // final broadcast row
__device__ float g_dummy[32];

// Keeps launch-ordinal mapping stable so ncu samples gemv_r each round.
__global__ void dummy_kernel() {
    g_dummy[threadIdx.x] = (float)threadIdx.x;
}

// g_v[f,j] = bc[f, E+j];  g_r[o] = sum_f bp[f, o]
__global__ void init_kernel(const float* __restrict__ bc,
                            const float* __restrict__ bp) {
    int i = blockIdx.x * blockDim.x + threadIdx.x;
    if (i < FDIM * EDIM) {
        int f = i >> 11;
        int j = i & (EDIM - 1);
        g_v[i] = bc[f * 2 * EDIM + EDIM + j];
    }
    if (i < EDIM) {
        float s = 0.0f;
#pragma unroll
        for (int f = 0; f < FDIM; f++) s += bp[f * EDIM + i];
        g_r[i] = s;
    }
}

// v[f, j..j+3] += sum_{e in 16-chunk} h_last[e] * Wc[f, e, E + j..j+3]
// grid: (EDIM/1024, NCHUNK, F) = (2, 128, 4) = 1024 blocks of 256 threads.
// float4 loads (better per-warp BW) at high occupancy (8 warps x 7 blk/SM).
__global__ void __launch_bounds__(256, 7)
gemv_v_kernel(const float* __restrict__ h_last,
              const float* __restrict__ Wc) {
    __shared__ float sh[ECHUNK];
    const int f  = blockIdx.z;
    const int j  = blockIdx.x * 1024 + threadIdx.x * 4;
    const int e0 = blockIdx.y * ECHUNK;

    if (threadIdx.x < ECHUNK) sh[threadIdx.x] = h_last[e0 + threadIdx.x];
    __syncthreads();

    const float* W = Wc + ((size_t)f * EDIM + e0) * (2 * EDIM) + EDIM + j;
    float4 acc = make_float4(0.f, 0.f, 0.f, 0.f);
#pragma unroll
    for (int e = 0; e < ECHUNK; e++) {
        float4 w = *reinterpret_cast<const float4*>(W + (size_t)e * (2 * EDIM));
        float hv = sh[e];
        acc.x = fmaf(hv, w.x, acc.x);
        acc.y = fmaf(hv, w.y, acc.y);
        acc.z = fmaf(hv, w.z, acc.z);
        acc.w = fmaf(hv, w.w, acc.w);
    }
    float* dst = &g_v[f * EDIM + j];
    atomicAdd(dst + 0, acc.x);
    atomicAdd(dst + 1, acc.y);
    atomicAdd(dst + 2, acc.z);
    atomicAdd(dst + 3, acc.w);
}

// r[o..o+3] += sum_f sum_{e in 16-chunk} v[f, e] * Wp[f, e, o..o+3]
__global__ void __launch_bounds__(256, 7)
gemv_r_kernel(const float* __restrict__ Wp) {
    __shared__ float sv[ECHUNK];
    const int f  = blockIdx.z;
    const int o  = blockIdx.x * 1024 + threadIdx.x * 4;
    const int e0 = blockIdx.y * ECHUNK;

    if (threadIdx.x < ECHUNK) sv[threadIdx.x] = g_v[f * EDIM + e0 + threadIdx.x];
    __syncthreads();

    const float* W = Wp + ((size_t)f * EDIM + e0) * EDIM + o;
    float4 acc = make_float4(0.f, 0.f, 0.f, 0.f);
#pragma unroll
    for (int e = 0; e < ECHUNK; e++) {
        float4 w = *reinterpret_cast<const float4*>(W + (size_t)e * EDIM);
        float vv = sv[e];
        acc.x = fmaf(vv, w.x, acc.x);
        acc.y = fmaf(vv, w.y, acc.y);
        acc.z = fmaf(vv, w.z, acc.z);
        acc.w = fmaf(vv, w.w, acc.w);
    }
    float* dst = &g_r[o];
    atomicAdd(dst + 0, acc.x);
    atomicAdd(dst + 1, acc.y);
    atomicAdd(dst + 2, acc.z);
    atomicAdd(dst + 3, acc.w);
}

// out[s, :] = r[:] for 8 rows per block via TMA bulk stores (512 blocks).
__global__ void __launch_bounds__(256)
bcast_kernel(float* __restrict__ out) {
    __shared__ __align__(128) float srow[EDIM];
    const float4* r4 = reinterpret_cast<const float4*>(g_r);
    float4* s4 = reinterpret_cast<float4*>(srow);
    s4[threadIdx.x]       = r4[threadIdx.x];
    s4[threadIdx.x + 256] = r4[threadIdx.x + 256];
    __syncthreads();
    asm volatile("fence.proxy.async.shared::cta;" ::: "memory");

    if (threadIdx.x == 0) {
        uint32_t saddr;
        asm("{ .reg .u64 t; cvta.to.shared.u64 t, %1; cvt.u32.u64 %0, t; }"
            : "=r"(saddr) : "l"(srow));
        size_t base = (size_t)blockIdx.x * 8 * EDIM;
        const uint32_t nbytes = EDIM * 4;
#pragma unroll
        for (int s = 0; s < 8; s++) {
            asm volatile(
                "cp.async.bulk.global.shared::cta.bulk_group [%0], [%1], %2;"
                :: "l"(out + base + (size_t)s * EDIM), "r"(saddr), "r"(nbytes)
                : "memory");
        }
        asm volatile("cp.async.bulk.commit_group;" ::: "memory");
        asm volatile("cp.async.bulk.wait_group 0;" ::: "memory");
    }
}

extern "C" void kernel_launch(void* const* d_in, const int* in_sizes, int n_in,
                              void* d_out, int out_size) {
    // order: hidden_states, encoder_hidden_states, Wq, bq, Wc, bc, Wp, bp
    const float* hidden = (const float*)d_in[0];
    const float* Wc     = (const float*)d_in[4];
    const float* bc     = (const float*)d_in[5];
    const float* Wp     = (const float*)d_in[6];
    const float* bp     = (const float*)d_in[7];
    float* out = (float*)d_out;

    const float* h_last = hidden + 127 * EDIM;  // hidden_states[0, -1, :]

    dummy_kernel<<<1, 32>>>();
    init_kernel<<<(FDIM * EDIM + 255) / 256, 256>>>(bc, bp);
    gemv_v_kernel<<<dim3(EDIM / 1024, NCHUNK, FDIM), 256>>>(h_last, Wc);
    gemv_r_kernel<<<dim3(EDIM / 1024, NCHUNK, FDIM), 256>>>(Wp);
    bcast_kernel<<<SOUT / 8, 256>>>(out);
}

// round 7
// speedup vs baseline: 1.4498x; 1.4498x over previous
#include <cuda_runtime.h>
#include <cstdint>

// GPT2Editor: softmax over a size-1 axis -> weights == 1, so
// out[s, :] = sum_f ( (h_last @ Wc[f][:, E:2E] + bc[f][E:]) @ Wp[f] + bp[f] )
// broadcast to all 4096 rows. Dead inputs: encoder_hidden_states, Wq, bq.
// E = 2048, F = 4.
//
// r4-r6 showed global atomics to the 8KB g_r/g_v regions serialize at the
// LTS (dur ~ linear in RED count). This version is 100% atomic-free:
// split-K partials go to dedicated buffers with plain stores, reduced by
// smem trees.

#define EDIM 2048
#define FDIM 4
#define SOUT 4096
#define ECHUNK 32
#define NCHUNK (EDIM / ECHUNK)          // 64
#define NPART (FDIM * NCHUNK)           // 256

__device__ float g_part_v[NPART * EDIM];  // per-(f,chunk) partials of v
__device__ float g_part_r[NPART * EDIM];  // per-(f,chunk) partials of r
__device__ float g_r[EDIM];               // final broadcast row
__device__ float g_dummy[32];

// Two dummies keep gemv_r at launch ordinal 4 (where ncu samples).
__global__ void dummy_kernel() {
    g_dummy[threadIdx.x] = (float)threadIdx.x;
}

// part_v[f][c][j..j+3] = sum_{e in chunk c} h_last[e] * Wc[f, e, E+j..j+3]
// grid (2, 64, 4) = 512 blocks of 256 threads. Plain float4 store, no atomics.
__global__ void __launch_bounds__(256)
gemv_v_kernel(const float* __restrict__ h_last,
              const float* __restrict__ Wc) {
    __shared__ float sh[ECHUNK];
    const int f  = blockIdx.z;
    const int c  = blockIdx.y;
    const int j  = blockIdx.x * 1024 + threadIdx.x * 4;
    const int e0 = c * ECHUNK;

    if (threadIdx.x < ECHUNK) sh[threadIdx.x] = h_last[e0 + threadIdx.x];
    __syncthreads();

    const float* W = Wc + ((size_t)f * EDIM + e0) * (2 * EDIM) + EDIM + j;
    float4 acc = make_float4(0.f, 0.f, 0.f, 0.f);
#pragma unroll
    for (int e = 0; e < ECHUNK; e++) {
        float4 w = *reinterpret_cast<const float4*>(W + (size_t)e * (2 * EDIM));
        float hv = sh[e];
        acc.x = fmaf(hv, w.x, acc.x);
        acc.y = fmaf(hv, w.y, acc.y);
        acc.z = fmaf(hv, w.z, acc.z);
        acc.w = fmaf(hv, w.w, acc.w);
    }
    *reinterpret_cast<float4*>(&g_part_v[((size_t)f * NCHUNK + c) * EDIM + j]) = acc;
}

// Assemble v[f, e0..e0+31] from the 64 part_v partials (+bc), then
// part_r[f][cr][o..o+3] = sum_{e in chunk} v[f,e] * Wp[f, e, o..o+3].
// grid (2, 64, 4) = 512 blocks of 256 threads. No atomics.
__global__ void __launch_bounds__(256)
gemv_r_kernel(const float* __restrict__ Wp,
              const float* __restrict__ bc) {
    __shared__ float red[8][ECHUNK];
    __shared__ float sv[ECHUNK];
    const int f  = blockIdx.z;
    const int cr = blockIdx.y;
    const int e0 = cr * ECHUNK;
    const int t  = threadIdx.x;

    // v-slice reduction: 64 partials -> 8 per thread -> smem tree.
    {
        const int c8 = t >> 5;       // 0..7
        const int e  = t & 31;
        float s = 0.0f;
#pragma unroll
        for (int k = 0; k < 8; k++)
            s += g_part_v[((size_t)f * NCHUNK + c8 + 8 * k) * EDIM + e0 + e];
        red[c8][e] = s;
    }
    __syncthreads();
    if (t < ECHUNK) {
        float a = bc[(size_t)f * 2 * EDIM + EDIM + e0 + t];
#pragma unroll
        for (int i = 0; i < 8; i++) a += red[i][t];
        sv[t] = a;
    }
    __syncthreads();

    const int o = blockIdx.x * 1024 + t * 4;
    const float* W = Wp + ((size_t)f * EDIM + e0) * EDIM + o;
    float4 acc = make_float4(0.f, 0.f, 0.f, 0.f);
#pragma unroll
    for (int e = 0; e < ECHUNK; e++) {
        float4 w = *reinterpret_cast<const float4*>(W + (size_t)e * EDIM);
        float vv = sv[e];
        acc.x = fmaf(vv, w.x, acc.x);
        acc.y = fmaf(vv, w.y, acc.y);
        acc.z = fmaf(vv, w.z, acc.z);
        acc.w = fmaf(vv, w.w, acc.w);
    }
    *reinterpret_cast<float4*>(&g_part_r[((size_t)f * NCHUNK + cr) * EDIM + o]) = acc;
}

// g_r[o] = sum over 256 part_r partials + sum_f bp[f,o].
// grid 64 blocks of 256 threads; block b covers outputs b*32..b*32+31.
__global__ void __launch_bounds__(256)
reduce_r_kernel(const float* __restrict__ bp) {
    __shared__ float red[8][32];
    const int t = threadIdx.x;
    const int p = t >> 5;        // 0..7
    const int o = blockIdx.x * 32 + (t & 31);

    float s = 0.0f;
#pragma unroll
    for (int k = 0; k < 32; k++)
        s += g_part_r[((size_t)p + 8 * k) * EDIM + o];
    red[p][t & 31] = s;
    __syncthreads();

    if (t < 32) {
        int oo = blockIdx.x * 32 + t;
        float a = 0.0f;
#pragma unroll
        for (int f = 0; f < FDIM; f++) a += bp[(size_t)f * EDIM + oo];
#pragma unroll
        for (int i = 0; i < 8; i++) a += red[i][t];
        g_r[oo] = a;
    }
}

// out[s, :] = r[:] for 8 rows per block via TMA bulk stores (512 blocks).
__global__ void __launch_bounds__(256)
bcast_kernel(float* __restrict__ out) {
    __shared__ __align__(128) float srow[EDIM];
    const float4* r4 = reinterpret_cast<const float4*>(g_r);
    float4* s4 = reinterpret_cast<float4*>(srow);
    s4[threadIdx.x]       = r4[threadIdx.x];
    s4[threadIdx.x + 256] = r4[threadIdx.x + 256];
    __syncthreads();
    asm volatile("fence.proxy.async.shared::cta;" ::: "memory");

    if (threadIdx.x == 0) {
        uint32_t saddr;
        asm("{ .reg .u64 t; cvta.to.shared.u64 t, %1; cvt.u32.u64 %0, t; }"
            : "=r"(saddr) : "l"(srow));
        size_t base = (size_t)blockIdx.x * 8 * EDIM;
        const uint32_t nbytes = EDIM * 4;
#pragma unroll
        for (int s = 0; s < 8; s++) {
            asm volatile(
                "cp.async.bulk.global.shared::cta.bulk_group [%0], [%1], %2;"
                :: "l"(out + base + (size_t)s * EDIM), "r"(saddr), "r"(nbytes)
                : "memory");
        }
        asm volatile("cp.async.bulk.commit_group;" ::: "memory");
        asm volatile("cp.async.bulk.wait_group 0;" ::: "memory");
    }
}

extern "C" void kernel_launch(void* const* d_in, const int* in_sizes, int n_in,
                              void* d_out, int out_size) {
    // order: hidden_states, encoder_hidden_states, Wq, bq, Wc, bc, Wp, bp
    const float* hidden = (const float*)d_in[0];
    const float* Wc     = (const float*)d_in[4];
    const float* bc     = (const float*)d_in[5];
    const float* Wp     = (const float*)d_in[6];
    const float* bp     = (const float*)d_in[7];
    float* out = (float*)d_out;

    const float* h_last = hidden + 127 * EDIM;  // hidden_states[0, -1, :]

    dummy_kernel<<<1, 32>>>();
    dummy_kernel<<<1, 32>>>();
    gemv_v_kernel<<<dim3(EDIM / 1024, NCHUNK, FDIM), 256>>>(h_last, Wc);
    gemv_r_kernel<<<dim3(EDIM / 1024, NCHUNK, FDIM), 256>>>(Wp, bc);
    reduce_r_kernel<<<EDIM / 32, 256>>>(bp);
    bcast_kernel<<<SOUT / 8, 256>>>(out);
}